// round 16
// baseline (speedup 1.0000x reference)
#include <cuda_runtime.h>
#include <cuda_fp16.h>
#include <cstddef>

#define NV 25000
#define NE 400000
#define H  192
#define BM 64
#define SCALE_UP 1024.0f
#define SCALE_DN (1.0f / 1024.0f)

// ---------------- scratch (static device globals; no runtime allocation) ---------
__device__ float  g_Y[(size_t)NV * H];    // aggregation output (fp32)
__device__ float  g_X[(size_t)NV * H];    // intra-block activation (fp32)
__device__ float  g_F[(size_t)NV * H];    // feats residual stream (fp32)
__device__ __half g_FEh[(size_t)NV * H];  // fp16 mirror of features (x * 2^-10)
__device__ __half g_Xh[(size_t)NV * H];   // fp16 mirror of X        (x * 2^-10)
__device__ __half g_Fh[(size_t)NV * H];   // fp16 mirror of F        (x * 2^-10)
__device__ int    g_rowptr[NV + 1];
__device__ int    g_cnt[NV];
__device__ int    g_fill[NV];
__device__ int2   g_edge[NE];             // packed (src, weight-bits)

// ---------------- CSR build ------------------------------------------------------
__global__ void k_zero2(int* a, int* b, int n) {
    int i = blockIdx.x * blockDim.x + threadIdx.x;
    if (i < n) { a[i] = 0; b[i] = 0; }
}

__global__ void k_hist(const int* __restrict__ dst, int* cnt, int E) {
    int i = blockIdx.x * blockDim.x + threadIdx.x;
    if (i < E) atomicAdd(&cnt[dst[i]], 1);
}

// single-kernel exclusive scan: one block, 1024 threads x 25 elements each
#define SCAN_PER_T 25
__global__ __launch_bounds__(1024) void k_scan1(const int* __restrict__ cnt,
                                                int* __restrict__ rowptr,
                                                int n, int E) {
    __shared__ int wsum[32];
    int t    = threadIdx.x;
    int lane = t & 31;
    int w    = t >> 5;
    int base = t * SCAN_PER_T;
    int loc[SCAN_PER_T];
    int s = 0;
#pragma unroll
    for (int j = 0; j < SCAN_PER_T; j++) {
        int i = base + j;
        int v = (i < n) ? cnt[i] : 0;
        loc[j] = s;
        s += v;
    }
    int x = s;
#pragma unroll
    for (int off = 1; off < 32; off <<= 1) {
        int u = __shfl_up_sync(0xffffffffu, x, off);
        if (lane >= off) x += u;
    }
    if (lane == 31) wsum[w] = x;
    int excl = x - s;
    __syncthreads();
    if (w == 0) {
        int p = wsum[lane];
        int y = p;
#pragma unroll
        for (int off = 1; off < 32; off <<= 1) {
            int u = __shfl_up_sync(0xffffffffu, y, off);
            if (lane >= off) y += u;
        }
        wsum[lane] = y;
    }
    __syncthreads();
    int offset = excl + (w > 0 ? wsum[w - 1] : 0);
#pragma unroll
    for (int j = 0; j < SCAN_PER_T; j++) {
        int i = base + j;
        if (i < n) rowptr[i] = offset + loc[j];
    }
    if (t == 0) rowptr[n] = E;
}

__global__ void k_scatter(const int* __restrict__ src, const int* __restrict__ dst,
                          const float* __restrict__ w, const int* __restrict__ rowptr,
                          int* fill, int2* edge, int E) {
    int i = blockIdx.x * blockDim.x + threadIdx.x;
    if (i < E) {
        int d = dst[i];
        int pos = rowptr[d] + atomicAdd(&fill[d], 1);
        edge[pos] = make_int2(src[i], __float_as_int(w[i]));
    }
}

// ---------------- fp32 -> fp16*2^-10 convert (features mirror) -------------------
__global__ void k_cvt_h(const float* __restrict__ src, __half* __restrict__ dst, int n2) {
    int i = blockIdx.x * blockDim.x + threadIdx.x;
    if (i < n2) {
        float2 v = ((const float2*)src)[i];
        ((__half2*)dst)[i] = __floats2half2_rn(v.x * SCALE_DN, v.y * SCALE_DN);
    }
}

// ---------------- sparse aggregation: Y[d] = 2^10 * sum_e w_e * Xh[src_e] --------
// one warp per destination vertex. ONE gather LDG per edge: lanes 0-23 each load
// uint4 (16B = 8 halves); lane owns cols lane*8 .. lane*8+7. fp32 accumulate.
__global__ __launch_bounds__(256) void k_agg(const __half* __restrict__ Xh,
                                             float* __restrict__ Y,
                                             const int* __restrict__ rowptr,
                                             const int2* __restrict__ edge, int M) {
    int warp = (blockIdx.x * blockDim.x + threadIdx.x) >> 5;
    int lane = threadIdx.x & 31;
    if (warp >= M) return;
    int beg = rowptr[warp], end = rowptr[warp + 1];
    bool act = lane < 24;
    float a0 = 0.f, a1 = 0.f, a2 = 0.f, a3 = 0.f,
          a4 = 0.f, a5 = 0.f, a6 = 0.f, a7 = 0.f;
#pragma unroll 4
    for (int e = beg; e < end; e++) {
        int2  ed = __ldg(edge + e);       // uniform across warp: 1 request, L1-hit
        float wt = __int_as_float(ed.y);
        if (act) {
            uint4 v = __ldg((const uint4*)(Xh + (size_t)ed.x * H) + lane);
            float2 f0 = __half22float2(*(const __half2*)&v.x);
            float2 f1 = __half22float2(*(const __half2*)&v.y);
            float2 f2 = __half22float2(*(const __half2*)&v.z);
            float2 f3 = __half22float2(*(const __half2*)&v.w);
            a0 += wt * f0.x; a1 += wt * f0.y;
            a2 += wt * f1.x; a3 += wt * f1.y;
            a4 += wt * f2.x; a5 += wt * f2.y;
            a6 += wt * f3.x; a7 += wt * f3.y;
        }
    }
    if (act) {
        float* o = Y + (size_t)warp * H + lane * 8;
        float4 o0, o1;
        o0.x = a0 * SCALE_UP; o0.y = a1 * SCALE_UP;
        o0.z = a2 * SCALE_UP; o0.w = a3 * SCALE_UP;
        o1.x = a4 * SCALE_UP; o1.y = a5 * SCALE_UP;
        o1.z = a6 * SCALE_UP; o1.w = a7 * SCALE_UP;
        *(float4*)o       = o0;
        *(float4*)(o + 4) = o1;
    }
}

// ---------------- tf32 tensor-core GEMM + fused epilogue -------------------------
// C = A[M,192] @ W[192,192];  out = relu(C + bias)                (mode 0)
//                             out = (res + relu(C + bias)) * 0.5  (mode 1)
// writes fp32 out, scaled fp16 mirror outh, optional second fp32 out2.
#define SA 36
#define SB 200

__device__ __forceinline__ unsigned f2tf32(float x) {
    unsigned u;
    asm("cvt.rna.tf32.f32 %0, %1;" : "=r"(u) : "f"(x));
    return u;
}

__device__ __forceinline__ void mma_tf32(float* c, const unsigned* a,
                                         unsigned b0, unsigned b1) {
    asm volatile(
        "mma.sync.aligned.m16n8k8.row.col.f32.tf32.tf32.f32 "
        "{%0,%1,%2,%3}, {%4,%5,%6,%7}, {%8,%9}, {%0,%1,%2,%3};"
        : "+f"(c[0]), "+f"(c[1]), "+f"(c[2]), "+f"(c[3])
        : "r"(a[0]), "r"(a[1]), "r"(a[2]), "r"(a[3]), "r"(b0), "r"(b1));
}

__global__ __launch_bounds__(256) void k_gemm_tf32(const float* __restrict__ A,
                                                   const float* __restrict__ Wm,
                                                   const float* __restrict__ bias,
                                                   const float* __restrict__ res,
                                                   float* __restrict__ out,
                                                   __half* __restrict__ outh,
                                                   float* __restrict__ out2,
                                                   int M, int mode) {
    __shared__ unsigned As[BM * SA];
    __shared__ unsigned Bs[32 * SB];

    int tid  = threadIdx.x;
    int lane = tid & 31;
    int warp = tid >> 5;
    int gid  = lane >> 2;
    int tig  = lane & 3;
    int rowg = warp & 1;
    int colg = warp >> 1;
    int m0   = blockIdx.x * BM;

    float c[2][6][4];
#pragma unroll
    for (int t = 0; t < 2; t++)
#pragma unroll
        for (int j = 0; j < 6; j++)
#pragma unroll
            for (int q = 0; q < 4; q++) c[t][j][q] = 0.f;

    int arow = tid >> 2;
    int akk  = (tid & 3) * 8;

    for (int it = 0; it < 6; it++) {
        int k0 = it * 32;
        __syncthreads();
        {
            int gr = m0 + arow;
            float4 v0 = make_float4(0.f, 0.f, 0.f, 0.f);
            float4 v1 = v0;
            if (gr < M) {
                const float* p = A + (size_t)gr * H + k0 + akk;
                v0 = *(const float4*)p;
                v1 = *(const float4*)(p + 4);
            }
            unsigned* d = &As[arow * SA + akk];
            d[0] = f2tf32(v0.x); d[1] = f2tf32(v0.y);
            d[2] = f2tf32(v0.z); d[3] = f2tf32(v0.w);
            d[4] = f2tf32(v1.x); d[5] = f2tf32(v1.y);
            d[6] = f2tf32(v1.z); d[7] = f2tf32(v1.w);
        }
#pragma unroll
        for (int i = 0; i < 6; i++) {
            int f4  = tid + 256 * i;
            int row = f4 / 48;
            int cc  = (f4 % 48) * 4;
            float4 w = *(const float4*)(Wm + (size_t)(k0 + row) * H + cc);
            unsigned* d = &Bs[row * SB + cc];
            d[0] = f2tf32(w.x); d[1] = f2tf32(w.y);
            d[2] = f2tf32(w.z); d[3] = f2tf32(w.w);
        }
        __syncthreads();
#pragma unroll
        for (int ks = 0; ks < 4; ks++) {
            int kk = ks * 8;
            unsigned a[2][4];
#pragma unroll
            for (int t = 0; t < 2; t++) {
                int r = rowg * 32 + t * 16 + gid;
                a[t][0] = As[r * SA + kk + tig];
                a[t][1] = As[(r + 8) * SA + kk + tig];
                a[t][2] = As[r * SA + kk + tig + 4];
                a[t][3] = As[(r + 8) * SA + kk + tig + 4];
            }
#pragma unroll
            for (int j = 0; j < 6; j++) {
                int n = colg * 48 + j * 8 + gid;
                unsigned b0 = Bs[(kk + tig) * SB + n];
                unsigned b1 = Bs[(kk + tig + 4) * SB + n];
                mma_tf32(c[0][j], a[0], b0, b1);
                mma_tf32(c[1][j], a[1], b0, b1);
            }
        }
    }

    float2 bb[6];
#pragma unroll
    for (int j = 0; j < 6; j++)
        bb[j] = *(const float2*)(bias + colg * 48 + j * 8 + tig * 2);

#pragma unroll
    for (int t = 0; t < 2; t++) {
#pragma unroll
        for (int h = 0; h < 2; h++) {
            int m = m0 + rowg * 32 + t * 16 + gid + h * 8;
            if (m < M) {
                size_t off = (size_t)m * H + colg * 48 + tig * 2;
                const float* rrow = res + off;
#pragma unroll
                for (int j = 0; j < 6; j++) {
                    float v0 = fmaxf(c[t][j][h * 2 + 0] + bb[j].x, 0.f);
                    float v1 = fmaxf(c[t][j][h * 2 + 1] + bb[j].y, 0.f);
                    if (mode == 1) {
                        float2 r2 = *(const float2*)(rrow + j * 8);
                        v0 = (r2.x + v0) * 0.5f;
                        v1 = (r2.y + v1) * 0.5f;
                    }
                    float2 o2; o2.x = v0; o2.y = v1;
                    *(float2*)(out + off + j * 8) = o2;
                    *(__half2*)(outh + off + j * 8) =
                        __floats2half2_rn(v0 * SCALE_DN, v1 * SCALE_DN);
                    if (out2) *(float2*)(out2 + off + j * 8) = o2;
                }
            }
        }
    }
}

// ---------------- fused output head: coords = (agg(Fh)*2^10) @ W_out + b_out -----
__global__ __launch_bounds__(256) void k_agg_head(const __half* __restrict__ Xh,
                                                  const int* __restrict__ rowptr,
                                                  const int2* __restrict__ edge,
                                                  const float* __restrict__ Wout,
                                                  const float* __restrict__ bout,
                                                  float* __restrict__ out, int M) {
    int warp = (blockIdx.x * blockDim.x + threadIdx.x) >> 5;
    int lane = threadIdx.x & 31;
    if (warp >= M) return;
    int beg = rowptr[warp], end = rowptr[warp + 1];
    bool act = lane < 24;
    float acc[8];
#pragma unroll
    for (int i = 0; i < 8; i++) acc[i] = 0.f;
#pragma unroll 4
    for (int e = beg; e < end; e++) {
        int2  ed = __ldg(edge + e);
        float wt = __int_as_float(ed.y);
        if (act) {
            uint4 v = __ldg((const uint4*)(Xh + (size_t)ed.x * H) + lane);
            float2 f0 = __half22float2(*(const __half2*)&v.x);
            float2 f1 = __half22float2(*(const __half2*)&v.y);
            float2 f2 = __half22float2(*(const __half2*)&v.z);
            float2 f3 = __half22float2(*(const __half2*)&v.w);
            acc[0] += wt * f0.x; acc[1] += wt * f0.y;
            acc[2] += wt * f1.x; acc[3] += wt * f1.y;
            acc[4] += wt * f2.x; acc[5] += wt * f2.y;
            acc[6] += wt * f3.x; acc[7] += wt * f3.y;
        }
    }
    float s0 = 0.f, s1 = 0.f, s2 = 0.f;
    if (act) {
#pragma unroll
        for (int i = 0; i < 8; i++) {
            int col = lane * 8 + i;
            const float* wr = Wout + (size_t)col * 3;
            s0 += acc[i] * __ldg(wr + 0);
            s1 += acc[i] * __ldg(wr + 1);
            s2 += acc[i] * __ldg(wr + 2);
        }
    }
#pragma unroll
    for (int off = 16; off; off >>= 1) {
        s0 += __shfl_down_sync(0xffffffffu, s0, off);
        s1 += __shfl_down_sync(0xffffffffu, s1, off);
        s2 += __shfl_down_sync(0xffffffffu, s2, off);
    }
    if (lane == 0) {
        out[(size_t)warp * 3 + 0] = s0 * SCALE_UP + __ldg(bout + 0);
        out[(size_t)warp * 3 + 1] = s1 * SCALE_UP + __ldg(bout + 1);
        out[(size_t)warp * 3 + 2] = s2 * SCALE_UP + __ldg(bout + 2);
    }
}

// ---------------- launch ---------------------------------------------------------
extern "C" void kernel_launch(void* const* d_in, const int* in_sizes, int n_in,
                              void* d_out, int out_size) {
    const float* features = (const float*)d_in[0];
    const int*   esrc     = (const int*)d_in[1];
    const int*   edst     = (const int*)d_in[2];
    const float* ew       = (const float*)d_in[3];
    const float* Ws       = (const float*)d_in[4];
    const float* bs       = (const float*)d_in[5];
    const float* Wout     = (const float*)d_in[6];
    const float* bout     = (const float*)d_in[7];
    float* out = (float*)d_out;

    int M = in_sizes[0] / H;   // 25000
    int E = in_sizes[1];       // 400000

    float *Y, *X, *F;
    __half *FEh, *Xh, *Fh;
    int *rp, *cnt, *fill;
    int2* edge;
    cudaGetSymbolAddress((void**)&Y, g_Y);
    cudaGetSymbolAddress((void**)&X, g_X);
    cudaGetSymbolAddress((void**)&F, g_F);
    cudaGetSymbolAddress((void**)&FEh, g_FEh);
    cudaGetSymbolAddress((void**)&Xh, g_Xh);
    cudaGetSymbolAddress((void**)&Fh, g_Fh);
    cudaGetSymbolAddress((void**)&rp, g_rowptr);
    cudaGetSymbolAddress((void**)&cnt, g_cnt);
    cudaGetSymbolAddress((void**)&fill, g_fill);
    cudaGetSymbolAddress((void**)&edge, g_edge);

    // ---- CSR build (by destination) + scaled fp16 feature mirror ----
    k_zero2<<<(M + 255) / 256, 256>>>(cnt, fill, M);
    k_hist<<<(E + 255) / 256, 256>>>(edst, cnt, E);
    k_cvt_h<<<((M * H / 2) + 255) / 256, 256>>>(features, FEh, M * H / 2);
    k_scan1<<<1, 1024>>>(cnt, rp, M, E);
    k_scatter<<<(E + 255) / 256, 256>>>(esrc, edst, ew, rp, fill, edge, E);

    int aggGrid  = (M * 32 + 255) / 256;
    int gemmGrid = (M + BM - 1) / BM;
    float* out_feats = (out_size >= M * 3 + M * H) ? (out + (size_t)M * 3) : nullptr;

    // layer 0: x = relu(gcn(features))
    k_agg<<<aggGrid, 256>>>(FEh, Y, rp, edge, M);
    k_gemm_tf32<<<gemmGrid, 256>>>(Y, Ws, bs, features /*unused*/, X, Xh, nullptr, M, 0);
    // layer 1: feats = (features + relu(gcn(x))) / 2
    k_agg<<<aggGrid, 256>>>(Xh, Y, rp, edge, M);
    k_gemm_tf32<<<gemmGrid, 256>>>(Y, Ws + (size_t)1 * H * H, bs + 1 * H,
                                   features, F, Fh, nullptr, M, 1);

    // blocks: layers (2,3) (4,5) (6,7) (8,9) (10,11)
    for (int l = 2; l < 12; l += 2) {
        k_agg<<<aggGrid, 256>>>(Fh, Y, rp, edge, M);
        k_gemm_tf32<<<gemmGrid, 256>>>(Y, Ws + (size_t)l * H * H, bs + (size_t)l * H,
                                       F /*unused*/, X, Xh, nullptr, M, 0);
        k_agg<<<aggGrid, 256>>>(Xh, Y, rp, edge, M);
        k_gemm_tf32<<<gemmGrid, 256>>>(Y, Ws + (size_t)(l + 1) * H * H,
                                       bs + (size_t)(l + 1) * H,
                                       F, F, Fh, nullptr, M, 1);
    }

    // gc13: feats = (feats + relu(gcn(feats))) / 2 ; dual-store into out feats region
    k_agg<<<aggGrid, 256>>>(Fh, Y, rp, edge, M);
    k_gemm_tf32<<<gemmGrid, 256>>>(Y, Ws + (size_t)12 * H * H, bs + (size_t)12 * H,
                                   F, F, Fh, out_feats, M, 1);

    // head: coords = gcn(feats) with W_out/b_out (no relu)
    k_agg_head<<<(M * 32 + 255) / 256, 256>>>(Fh, rp, edge, Wout, bout, out, M);
}